// round 16
// baseline (speedup 1.0000x reference)
#include <cuda_runtime.h>
#include <math.h>
#include <stdint.h>

#define BB 64      // batch
#define SS 64      // seq
#define IND 512    // input dim
#define HH 512     // hidden dim
#define G4 2048    // 4*H
#define NBLK 128   // persistent CTAs, phase 2
#define THR2 512   // phase-2 threads (16 warps)

typedef unsigned long long ull;

// ---------------- packed fp32x2 (FFMA2) ----------------
__device__ __forceinline__ void ffma2(ull& d, ull a, ull b) {
    asm("fma.rn.f32x2 %0, %1, %2, %0;" : "+l"(d) : "l"(a), "l"(b));
}
__device__ __forceinline__ float2 upk2(ull v) {
    float2 r; asm("mov.b64 {%0, %1}, %2;" : "=f"(r.x), "=f"(r.y) : "l"(v)); return r;
}

// ---------------- cp.async ----------------
__device__ __forceinline__ uint32_t smem_u32(const void* p) {
    uint32_t a;
    asm("{ .reg .u64 t; cvta.to.shared.u64 t, %1; cvt.u32.u64 %0, t; }" : "=r"(a) : "l"(p));
    return a;
}
__device__ __forceinline__ void cp16(uint32_t dst, const void* src) {
    uint64_t g; asm("cvta.to.global.u64 %0, %1;" : "=l"(g) : "l"(src));
    asm volatile("cp.async.cg.shared.global [%0], [%1], 16;" :: "r"(dst), "l"(g) : "memory");
}
#define CP_COMMIT() asm volatile("cp.async.commit_group;" ::: "memory")
#define CP_WAIT(n)  asm volatile("cp.async.wait_group %0;" :: "n"(n) : "memory")

// ---------------- device scratch ----------------
__device__ float g_Gx[(size_t)SS * G4 * BB];   // [s][row=gate*512+col][b]
__device__ float g_h[2][BB * HH];
__device__ unsigned int g_arrive;              // monotonic barrier counter (reset by phase 1)

__device__ __forceinline__ void grid_sync_step(unsigned int target) {
    __syncthreads();
    if (threadIdx.x == 0) {
        asm volatile("red.release.gpu.add.u32 [%0], 1;" :: "l"(&g_arrive) : "memory");
        unsigned int v;
        do {
            asm volatile("ld.acquire.gpu.u32 %0, [%1];"
                         : "=r"(v) : "l"(&g_arrive) : "memory");
        } while (v < target);
    }
    __syncthreads();
}

__device__ __forceinline__ float sigf(float x) { return 1.f / (1.f + __expf(-x)); }
__device__ __forceinline__ float tanhx(float x) {
    return 1.f - __fdividef(2.f, __expf(2.f * x) + 1.f);
}

// =====================================================================
// Phase 1: unchanged from R15 (8x8 microtile, cp.async dbuf, 2 CTAs/SM)
// =====================================================================
#define AROW 68
#define P1_BUF ((64 + 128) * AROW)
#define P1_SMEM (2 * P1_BUF * 4)

__global__ __launch_bounds__(128, 2) void gemm_x_kernel(
    const float* __restrict__ x, const float* __restrict__ Wih) {
    extern __shared__ float sm[];
    const int tid = threadIdx.x;
    const int tb = tid & 7, tr = tid >> 3;
    const int jt = blockIdx.x, s = blockIdx.y;

    if (jt == 0 && s == 0 && tid == 0) g_arrive = 0;

    ull acc[8][8];
#pragma unroll
    for (int i = 0; i < 8; i++)
#pragma unroll
        for (int j = 0; j < 8; j++) acc[i][j] = 0ull;

    {
        float* base = sm;
#pragma unroll 4
        for (int p = 0; p < 8; p++) {
            int fi = tid + 128 * p, b = fi >> 4, f = fi & 15;
            cp16(smem_u32(base + b * AROW + f * 4),
                 x + ((size_t)b * SS + s) * IND + f * 4);
        }
#pragma unroll 4
        for (int p = 0; p < 16; p++) {
            int fi = tid + 128 * p, r = fi >> 4, f = fi & 15;
            cp16(smem_u32(base + 64 * AROW + r * AROW + f * 4),
                 Wih + ((size_t)s * G4 + jt * 128 + r) * IND + f * 4);
        }
        CP_COMMIT();
    }

    for (int c = 0; c < 8; c++) {
        CP_WAIT(0);
        __syncthreads();
        if (c + 1 < 8) {
            float* base = sm + ((c + 1) & 1) * P1_BUF;
            int k0 = (c + 1) * 64;
#pragma unroll 4
            for (int p = 0; p < 8; p++) {
                int fi = tid + 128 * p, b = fi >> 4, f = fi & 15;
                cp16(smem_u32(base + b * AROW + f * 4),
                     x + ((size_t)b * SS + s) * IND + k0 + f * 4);
            }
#pragma unroll 4
            for (int p = 0; p < 16; p++) {
                int fi = tid + 128 * p, r = fi >> 4, f = fi & 15;
                cp16(smem_u32(base + 64 * AROW + r * AROW + f * 4),
                     Wih + ((size_t)s * G4 + jt * 128 + r) * IND + k0 + f * 4);
            }
            CP_COMMIT();
        } else {
            CP_COMMIT();
        }

        const float* ab = sm + (c & 1) * P1_BUF + tb * AROW;
        const float* wb = sm + (c & 1) * P1_BUF + 64 * AROW + tr * AROW;
#pragma unroll 2
        for (int q = 0; q < 16; q++) {
            const int o = q * 4;
            ulonglong2 a2[8];
#pragma unroll
            for (int bb = 0; bb < 8; bb++)
                a2[bb] = *(const ulonglong2*)(ab + bb * (8 * AROW) + o);
#pragma unroll
            for (int rr = 0; rr < 8; rr++) {
                ulonglong2 w2 = *(const ulonglong2*)(wb + rr * (16 * AROW) + o);
#pragma unroll
                for (int bb = 0; bb < 8; bb++) {
                    ffma2(acc[bb][rr], a2[bb].x, w2.x);
                    ffma2(acc[bb][rr], a2[bb].y, w2.y);
                }
            }
        }
        __syncthreads();
    }

#pragma unroll
    for (int rr = 0; rr < 8; rr++) {
        int row = jt * 128 + tr + 16 * rr;
        float* dst = g_Gx + ((size_t)s * G4 + row) * BB + tb;
#pragma unroll
        for (int bb = 0; bb < 8; bb++) {
            float2 u = upk2(acc[bb][rr]);
            dst[8 * bb] = u.x + u.y;
        }
    }
}

// =====================================================================
// Phase 2: persistent recurrence, 128 CTAs x 512 threads (16 warps).
// warp w: b-group wb=w&7 (batches 8wb..8wb+7), k-half kh=w>>3.
// lane = ks*4+j; lane k-slice = 32-k block (kh*8+ks), block m at 36m.
// Each warp stages its own 8 h-rows x its k-half -> __syncwarp only.
// kh=1 warps write selected partials to 4KB smem; one __syncthreads;
// kh=0 warps add partner partial + Gx, epilogue, store. HROW=584.
// =====================================================================
#define HROW 584
#define SH_H (BB * HROW)                   // 37376 floats
#define WBUF (16 * HROW)                   // 9344 floats
#define SH_P (SH_H + 2 * WBUF)             // partial exchange offset
#define P2_SMEM ((SH_P + 1024) * 4)        // 228352 B

#define SKOFS(kf) ((kf) + (((kf) >> 5) << 2))

__global__ __launch_bounds__(THR2, 1) void lstm_rec_kernel(
    const float* __restrict__ Whh, float* __restrict__ out) {
    extern __shared__ float sm[];
    float* sh_h = sm;                      // [64][HROW]
    float* sh_W = sm + SH_H;               // 2 x [16][HROW]
    float* sh_p = sm + SH_P;               // [8 warps][32 lanes][4]

    const int tid  = threadIdx.x;
    const int w    = tid >> 5;
    const int lane = tid & 31;
    const int j    = lane & 3;
    const int ks   = lane >> 2;
    const int wb   = w & 7;                // b-group
    const int kh   = w >> 3;               // k-half
    const int jh0  = blockIdx.x * 4;
    const int myb  = 8 * wb + ks;
    const int jh   = jh0 + j;

    if (tid < 256) g_h[0][blockIdx.x * 256 + tid] = 0.f;

    // stage W[0] -> buffer 0 (all 512 threads, 4 f4 each)
#pragma unroll
    for (int p = 0; p < 4; p++) {
        int fi = p * THR2 + tid;           // 0..2047
        int r = fi >> 7, kf = (fi & 127) * 4;
        int grow = (r >> 2) * 512 + jh0 + (r & 3);
        cp16(smem_u32(sh_W + r * HROW + SKOFS(kf)),
             Whh + (size_t)grow * HH + kf);
    }
    CP_COMMIT();
    CP_WAIT(0);

    float c = 0.f;
    unsigned int target = NBLK;
    grid_sync_step(target);

    for (int s = 0; s < SS; s++) {
        const int cur = s & 1, nxt = cur ^ 1;

        // Gx prefetch (epilogue lanes only; whole step to hide)
        float gx0, gx1, gx2, gx3;
        if (kh == 0) {
            const float* gxp = g_Gx + (size_t)s * G4 * BB;
            gx0 = gxp[(size_t)(0 * 512 + jh) * BB + myb];
            gx1 = gxp[(size_t)(1 * 512 + jh) * BB + myb];
            gx2 = gxp[(size_t)(2 * 512 + jh) * BB + myb];
            gx3 = gxp[(size_t)(3 * 512 + jh) * BB + myb];
        }

        // per-warp h staging: rows 8wb..8wb+7, k-half kh (16 f4/thread)
        {
            const float* hsrc = g_h[cur] + (8 * wb) * HH + kh * 256;
            float* hdst = sh_h + (8 * wb) * HROW;
#pragma unroll 4
            for (int p = 0; p < 16; p++) {
                int fi = p * 32 + lane;            // 0..511
                int r8 = fi >> 6, kf = (fi & 63) * 4;
                int kfg = kh * 256 + kf;
                cp16(smem_u32(hdst + r8 * HROW + SKOFS(kfg)),
                     hsrc + r8 * HH + kf);
            }
        }
        CP_COMMIT();                               // group A (h)
        // W[s+1] prefetch (CTA-spread; published by next grid barrier)
        if (s + 1 < SS) {
            const float* wsrc = Whh + (size_t)(s + 1) * G4 * HH;
            float* wdst = sh_W + nxt * WBUF;
#pragma unroll
            for (int p = 0; p < 4; p++) {
                int fi = p * THR2 + tid;
                int r = fi >> 7, kf = (fi & 127) * 4;
                int grow = (r >> 2) * 512 + jh0 + (r & 3);
                cp16(smem_u32(wdst + r * HROW + SKOFS(kf)),
                     wsrc + (size_t)grow * HH + kf);
            }
        }
        CP_COMMIT();                               // group B (W)

        CP_WAIT(1);                                // own h landed
        __syncwarp();

        // ---- GEMM slice: acc[8b][4g] over this lane's 32 k ----
        ull acc[8][4];
#pragma unroll
        for (int bb = 0; bb < 8; bb++)
#pragma unroll
            for (int g = 0; g < 4; g++) acc[bb][g] = 0ull;

        const int kbase = kh * 288 + 36 * ks;
        const float* hb0 = sh_h + (8 * wb) * HROW + kbase;
        const float* wb0 = sh_W + cur * WBUF + j * HROW + kbase;

#pragma unroll
        for (int q = 0; q < 8; q++) {
            const int o = q * 4;
            ulonglong2 w0 = *(const ulonglong2*)(wb0 + o);
            ulonglong2 w1 = *(const ulonglong2*)(wb0 + 4 * HROW + o);
            ulonglong2 w2 = *(const ulonglong2*)(wb0 + 8 * HROW + o);
            ulonglong2 w3 = *(const ulonglong2*)(wb0 + 12 * HROW + o);
#pragma unroll
            for (int bb = 0; bb < 8; bb++) {
                ulonglong2 h2 = *(const ulonglong2*)(hb0 + bb * HROW + o);
                ffma2(acc[bb][0], h2.x, w0.x); ffma2(acc[bb][0], h2.y, w0.y);
                ffma2(acc[bb][1], h2.x, w1.x); ffma2(acc[bb][1], h2.y, w1.y);
                ffma2(acc[bb][2], h2.x, w2.x); ffma2(acc[bb][2], h2.y, w2.y);
                ffma2(acc[bb][3], h2.x, w3.x); ffma2(acc[bb][3], h2.y, w3.y);
            }
        }

        // unpack + butterfly over ks (totals for this k-half on all lanes)
        float r[8][4];
#pragma unroll
        for (int bb = 0; bb < 8; bb++)
#pragma unroll
            for (int g = 0; g < 4; g++) {
                float2 u = upk2(acc[bb][g]);
                r[bb][g] = u.x + u.y;
            }
#pragma unroll
        for (int m = 4; m <= 16; m <<= 1)
#pragma unroll
            for (int bb = 0; bb < 8; bb++)
#pragma unroll
                for (int g = 0; g < 4; g++)
                    r[bb][g] += __shfl_xor_sync(0xffffffffu, r[bb][g], m);

        // select this lane's batch (bb == ks)
        float a0 = r[0][0], a1 = r[0][1], a2 = r[0][2], a3 = r[0][3];
#pragma unroll
        for (int bb = 1; bb < 8; bb++)
            if (ks == bb) { a0 = r[bb][0]; a1 = r[bb][1]; a2 = r[bb][2]; a3 = r[bb][3]; }

        // k-half combine: kh=1 writes partial, kh=0 consumes after sync
        if (kh == 1)
            *(float4*)&sh_p[(wb * 32 + lane) * 4] = make_float4(a0, a1, a2, a3);
        __syncthreads();

        if (kh == 0) {
            float4 pp = *(const float4*)&sh_p[(wb * 32 + lane) * 4];
            a0 += pp.x + gx0;
            a1 += pp.y + gx1;
            a2 += pp.z + gx2;
            a3 += pp.w + gx3;
            float ig = sigf(a0);
            float fg = sigf(a1);
            float gg = tanhx(a2);
            float og = sigf(a3);
            c = fg * c + ig * gg;
            float hv = og * tanhx(c);
            g_h[nxt][myb * HH + jh] = hv;
            out[((size_t)myb * SS + s) * HH + jh] = hv;
        }

        CP_WAIT(0);                                // own W[s+1] landed
        if (s + 1 < SS) {
            target += NBLK;
            grid_sync_step(target);                // publishes W + h CTA/grid-wide
        }
    }
}

// ---------------------------------------------------------------------
extern "C" void kernel_launch(void* const* d_in, const int* in_sizes, int n_in,
                              void* d_out, int out_size) {
    const float* x   = (const float*)d_in[0];
    const float* Wih = (const float*)d_in[1];
    const float* Whh = (const float*)d_in[2];
    float* out = (float*)d_out;

    cudaFuncSetAttribute(gemm_x_kernel,
                         cudaFuncAttributeMaxDynamicSharedMemorySize, P1_SMEM);
    cudaFuncSetAttribute(lstm_rec_kernel,
                         cudaFuncAttributeMaxDynamicSharedMemorySize, P2_SMEM);

    dim3 g1(16, 64);
    gemm_x_kernel<<<g1, 128, P1_SMEM>>>(x, Wih);
    lstm_rec_kernel<<<NBLK, THR2, P2_SMEM>>>(Whh, out);
}